// round 17
// baseline (speedup 1.0000x reference)
#include <cuda_runtime.h>
#include <cstdint>

// image [B=4, C=1, D=128, H=256, W=256] fp32
// out   [B, 2, D, H, W]: ch0 = copy, ch1 = sqrt(Gx^2+Gy^2+Gz^2 + 1e-8)
#define DIM_D 128
#define DIM_H 256
#define DIM_W 256
#define PLANE (DIM_H * DIM_W)
#define DCHUNK 64
#define NROWS 4                     // rows h0-1 .. h0+2 staged per plane
#define STAGE_F (NROWS * DIM_W)     // 1024 floats = 4 KB per buffer

typedef unsigned long long u64;

// ---- packed f32x2 helpers (sm_100+) ----
__device__ __forceinline__ u64 pk(float lo, float hi) {
    u64 r; asm("mov.b64 %0, {%1, %2};" : "=l"(r) : "f"(lo), "f"(hi)); return r;
}
__device__ __forceinline__ void upk(u64 a, float& lo, float& hi) {
    asm("mov.b64 {%0, %1}, %2;" : "=f"(lo), "=f"(hi) : "l"(a));
}
__device__ __forceinline__ u64 add2(u64 a, u64 b) {
    u64 r; asm("add.rn.f32x2 %0, %1, %2;" : "=l"(r) : "l"(a), "l"(b)); return r;
}
__device__ __forceinline__ u64 fma2(u64 a, u64 b, u64 c) {
    u64 r; asm("fma.rn.f32x2 %0, %1, %2, %3;" : "=l"(r) : "l"(a), "l"(b), "l"(c)); return r;
}
#define TWO2 0x4000000040000000ULL   // (2.0f, 2.0f)
#define NEG2 0xBF800000BF800000ULL   // (-1.0f, -1.0f)
#define EPS2 0x322BCC77322BCC77ULL   // (1e-8f, 1e-8f)

// .cg = global->L2->smem, no L1 allocation (16B only).
__device__ __forceinline__ void cp16(uint32_t saddr, const float* gp) {
    asm volatile("cp.async.cg.shared.global [%0], [%1], 16;" :: "r"(saddr), "l"(gp));
}
__device__ __forceinline__ void cp_commit() { asm volatile("cp.async.commit_group;"); }
__device__ __forceinline__ void cp_wait1()  { asm volatile("cp.async.wait_group 1;" ::: "memory"); }
__device__ __forceinline__ void cp_wait2()  { asm volatile("cp.async.wait_group 2;" ::: "memory"); }

// Single-instruction approximate sqrt (MUFU.SQRT), ~1 ulp: fine vs 1e-3 tol.
__device__ __forceinline__ float sqrt_fast(float x) {
    float r; asm("sqrt.approx.f32 %0, %1;" : "=f"(r) : "f"(x)); return r;
}

// Fold one staged plane into packed separable partials.
// Halos via warp shuffle (scalar); only warp-boundary lanes touch smem.
//   A = s_h*s_w(x) (Gz=d_d(A)); B = s_h*d_w(x) (Gx=s_d(B)); C = d_h*s_w(x) (Gy=s_d(C))
__device__ __forceinline__ void fold_smem(
    const float* __restrict__ sB,   // &sbuf[s][ty*DIM_W + w0]
    int lane, bool edge_l, bool edge_r,
    u64& Alo, u64& Ahi, u64& Blo, u64& Bhi, u64& Clo, u64& Chi,
    float4* cen)
{
#pragma unroll
    for (int r = 0; r < 3; r++) {
        const float* row = sB + r * DIM_W;
        const float4 c = *reinterpret_cast<const float4*>(row);

        float xl = __shfl_up_sync(0xffffffffu, c.w, 1);
        if (lane == 0)  xl = edge_l ? 0.f : row[-1];
        float xr = __shfl_down_sync(0xffffffffu, c.x, 1);
        if (lane == 31) xr = edge_r ? 0.f : row[4];

        if (r == 1 && cen) *cen = c;

        const u64 clo = pk(c.x, c.y);   // aligned pair from LDS.128 (free)
        const u64 chi = pk(c.z, c.w);   // aligned pair (free)
        const u64 L   = pk(xl,  c.x);
        const u64 M   = pk(c.y, c.z);
        const u64 R   = pk(c.w, xr);

        const u64 ulo = fma2(clo, TWO2, add2(L, M));   // s_w
        const u64 uhi = fma2(chi, TWO2, add2(M, R));
        const u64 vlo = fma2(L, NEG2, M);              // d_w = right - left
        const u64 vhi = fma2(M, NEG2, R);

        if (r == 0) {
            Alo = ulo; Ahi = uhi;
            Blo = vlo; Bhi = vhi;
            Clo = ulo; Chi = uhi;                      // holds u0 until r==2
        } else if (r == 1) {
            Alo = fma2(ulo, TWO2, Alo); Ahi = fma2(uhi, TWO2, Ahi);
            Blo = fma2(vlo, TWO2, Blo); Bhi = fma2(vhi, TWO2, Bhi);
        } else {
            Alo = add2(Alo, ulo); Ahi = add2(Ahi, uhi);
            Blo = add2(Blo, vlo); Bhi = add2(Bhi, vhi);
            Clo = fma2(Clo, NEG2, ulo);                // u2 - u0
            Chi = fma2(Chi, NEG2, uhi);
        }
    }
}

__global__ void __launch_bounds__(128, 8)
sobel_edge_kernel(const float* __restrict__ img, float* __restrict__ out)
{
    __shared__ float sbuf[3][STAGE_F];   // 12 KB

    const int tx  = threadIdx.x;           // 0..63 -> w (float4)
    const int ty  = threadIdx.y;           // 0..1  -> h row
    const int tid = tx + ty * 64;           // 0..127
    const int lane = tx & 31;
    const int w0  = tx * 4;
    const int h0  = blockIdx.x * 2;
    const int h   = h0 + ty;
    const int d0  = blockIdx.y * DCHUNK;
    const int b   = blockIdx.z;

    const bool edge_l = (tx & 32) == 0;    // warp lane0 at w0==0
    const bool edge_r = (tx & 32) != 0;    // warp lane31 at w0==252

    const float* gbase = img + (size_t)b * (DIM_D * PLANE);

    // staging: 256 16B chunks (4 rows x 64 float4) per plane, 128 threads x 2
    const int r0 = tid >> 6,          c0 = tid & 63;          // rows 0,1
    const int r1 = (tid + 128) >> 6,  c1 = (tid + 128) & 63;  // rows 2,3
    const int g0 = h0 - 1 + r0;
    const int g1 = h0 - 1 + r1;
    const bool gv0 = (g0 >= 0) && (g0 < DIM_H);
    const bool gv1 = (g1 >= 0) && (g1 < DIM_H);
    const float* gr0 = gbase + (size_t)g0 * DIM_W + c0 * 4;   // + p*PLANE at use
    const float* gr1 = gbase + (size_t)g1 * DIM_W + c1 * 4;
    const uint32_t sB0 = (uint32_t)__cvta_generic_to_shared(&sbuf[0][0]);
    const uint32_t so0 = (uint32_t)(r0 * DIM_W + c0 * 4) * 4u;
    const uint32_t so1 = (uint32_t)(r1 * DIM_W + c1 * 4) * 4u;
    float* z0 = &sbuf[0][r0 * DIM_W + c0 * 4];  // generic ptrs for zero-fill
    float* z1 = &sbuf[0][r1 * DIM_W + c1 * 4];

    const float4 f4z = make_float4(0.f, 0.f, 0.f, 0.f);

    // Stage plane p into buffer s (zero-fills invalid plane/rows). Always commits.
    auto stage = [&](int s, int p, bool need) {
        if (need) {
            const bool pv = (p >= 0) && (p < DIM_D);
            const size_t poff = (size_t)p * PLANE;
            const uint32_t sbase = sB0 + (uint32_t)s * (STAGE_F * 4u);
            if (pv && gv0) cp16(sbase + so0, gr0 + poff);
            else *reinterpret_cast<float4*>(z0 + s * STAGE_F) = f4z;
            if (pv && gv1) cp16(sbase + so1, gr1 + poff);
            else *reinterpret_cast<float4*>(z1 + s * STAGE_F) = f4z;
        }
        cp_commit();
    };

    // Output pointers
    float* o0 = out + (size_t)b * 2 * (DIM_D * PLANE)
              + (size_t)d0 * PLANE + (size_t)h * DIM_W + w0;   // copy ch, plane d0
    float* o1 = o0 + (size_t)(DIM_D * PLANE);                  // mag ch, plane d0
    const float* sMy = &sbuf[0][ty * DIM_W + w0];              // fold window, buf0

    // packed ring: slot0 = plane d-1, slot1 = d, slot2 = d+1
    u64 A0l, A0h, B0l, B0h, C0l, C0h;
    u64 A1l, A1h, B1l, B1h, C1l, C1h;
    u64 A2l, A2h, B2l, B2h, C2l, C2h;
    float4 cen;

    // --- prologue: stage planes d0-1, d0, d0+1 into bufs 0,1,2 ---
    stage(0, d0 - 1, true);
    stage(1, d0,     true);
    stage(2, d0 + 1, true);
    cp_wait2();
    __syncthreads();
    fold_smem(sMy, lane, edge_l, edge_r,
              A1l, A1h, B1l, B1h, C1l, C1h, nullptr);                 // d0-1
    cp_wait1();
    __syncthreads();
    fold_smem(sMy + STAGE_F, lane, edge_l, edge_r,
              A2l, A2h, B2l, B2h, C2l, C2h, &cen);                    // d0
    __stcs(reinterpret_cast<float4*>(o0), cen);                       // copy(d0)
    o0 += PLANE;                                                      // -> d0+1

    int sw = 0;   // write buffer for this iter
    int sr = 2;   // read (fold) buffer for this iter

#pragma unroll 3
    for (int dd = 0; dd < DCHUNK; dd++) {
        // (1) stage plane d0+dd+2 into buf sw (not needed on last iter)
        stage(sw, d0 + dd + 2, dd < DCHUNK - 1);

        // (2) wait for plane d0+dd+1 (committed 2 groups ago), sync, fold it
        cp_wait1();
        __syncthreads();
        A0l = A1l; A0h = A1h; B0l = B1l; B0h = B1h; C0l = C1l; C0h = C1h;
        A1l = A2l; A1h = A2h; B1l = B2l; B1h = B2h; C1l = C2l; C1h = C2h;
        fold_smem(&sbuf[sr][ty * DIM_W + w0], lane, edge_l, edge_r,
                  A2l, A2h, B2l, B2h, C2l, C2h, &cen);
        if (dd < DCHUNK - 1) {                    // copy(d0+dd+1) owned by this chunk
            __stcs(reinterpret_cast<float4*>(o0), cen);
        }
        o0 += PLANE;

        // (3) magnitude for plane d0+dd, packed (4 MUFU total)
        const u64 gxl = fma2(B1l, TWO2, add2(B0l, B2l));
        const u64 gxh = fma2(B1h, TWO2, add2(B0h, B2h));
        const u64 gyl = fma2(C1l, TWO2, add2(C0l, C2l));
        const u64 gyh = fma2(C1h, TWO2, add2(C0h, C2h));
        const u64 gzl = fma2(A0l, NEG2, A2l);        // A2 - A0
        const u64 gzh = fma2(A0h, NEG2, A2h);
        const u64 ssl = fma2(gxl, gxl, fma2(gyl, gyl, fma2(gzl, gzl, EPS2)));
        const u64 ssh = fma2(gxh, gxh, fma2(gyh, gyh, fma2(gzh, gzh, EPS2)));
        float4 m;
        upk(ssl, m.x, m.y);
        upk(ssh, m.z, m.w);
        m.x = sqrt_fast(m.x); m.y = sqrt_fast(m.y);
        m.z = sqrt_fast(m.z); m.w = sqrt_fast(m.w);

        __stcs(reinterpret_cast<float4*>(o1), m);
        o1 += PLANE;

        // advance buffer ring (constant after unroll-3 copy propagation)
        sw = (sw == 2) ? 0 : sw + 1;
        sr = (sr == 2) ? 0 : sr + 1;
    }
}

extern "C" void kernel_launch(void* const* d_in, const int* in_sizes, int n_in,
                              void* d_out, int out_size)
{
    const float* img = (const float*)d_in[0];
    float* out = (float*)d_out;

    dim3 block(64, 2, 1);                        // 128 threads
    dim3 grid(DIM_H / 2, DIM_D / DCHUNK, 4);     // 128 x 2 x 4 = 1024 CTAs (1 wave @8/SM)

    sobel_edge_kernel<<<grid, block>>>(img, out);
}